// round 15
// baseline (speedup 1.0000x reference)
#include <cuda_runtime.h>
#include <stdint.h>

// ===========================================================================
// JAX threefry2x32 (exact)
// ===========================================================================
static void threefry2x32_host(
    uint32_t k0, uint32_t k1, uint32_t x0, uint32_t x1,
    uint32_t& o0, uint32_t& o1)
{
    uint32_t ks2 = k0 ^ k1 ^ 0x1BD11BDAu;
    x0 += k0; x1 += k1;
#define TF_RNDH(R) { x0 += x1; x1 = (x1 << (R)) | (x1 >> (32 - (R))); x1 ^= x0; }
    TF_RNDH(13) TF_RNDH(15) TF_RNDH(26) TF_RNDH(6)   x0 += k1;  x1 += ks2 + 1u;
    TF_RNDH(17) TF_RNDH(29) TF_RNDH(16) TF_RNDH(24)  x0 += ks2; x1 += k0  + 2u;
    TF_RNDH(13) TF_RNDH(15) TF_RNDH(26) TF_RNDH(6)   x0 += k0;  x1 += k1  + 3u;
    TF_RNDH(17) TF_RNDH(29) TF_RNDH(16) TF_RNDH(24)  x0 += k1;  x1 += ks2 + 4u;
    TF_RNDH(13) TF_RNDH(15) TF_RNDH(26) TF_RNDH(6)   x0 += ks2; x1 += k0  + 5u;
#undef TF_RNDH
    o0 = x0; o1 = x1;
}

// keep-decision for flat element e: partitionable threefry counter (0, e),
// XOR-fold, uniform<0.8f as EXACT integer compare: bits < 0xCCCCCE00 (R9-verified)
__device__ __forceinline__ uint32_t tf_keep(uint32_t k0, uint32_t k1, uint32_t ks2,
                                            uint32_t e)
{
    uint32_t x0 = k0, x1 = e + k1;
#define TF_RND(R) { x0 += x1; x1 = __funnelshift_l(x1, x1, R); x1 ^= x0; }
    TF_RND(13) TF_RND(15) TF_RND(26) TF_RND(6)   x0 += k1;  x1 += ks2 + 1u;
    TF_RND(17) TF_RND(29) TF_RND(16) TF_RND(24)  x0 += ks2; x1 += k0  + 2u;
    TF_RND(13) TF_RND(15) TF_RND(26) TF_RND(6)   x0 += k0;  x1 += k1  + 3u;
    TF_RND(17) TF_RND(29) TF_RND(16) TF_RND(24)  x0 += k1;  x1 += ks2 + 4u;
    TF_RND(13) TF_RND(15) TF_RND(26) TF_RND(6)   x0 += ks2; x1 += k0  + 5u;
#undef TF_RND
    return ((x0 ^ x1) < 0xCCCCCE00u) ? 1u : 0u;
}

// ===========================================================================
// Primitives (baseline PTX — valid on compute_103 non-'a')
// ===========================================================================
__device__ __forceinline__ uint32_t smem_u32(const void* p) {
    uint32_t a;
    asm("{ .reg .u64 t; cvta.to.shared.u64 t, %1; cvt.u32.u64 %0, t; }"
        : "=r"(a) : "l"(p));
    return a;
}
__device__ __forceinline__ void ldm4(uint32_t addr,
    uint32_t& r0, uint32_t& r1, uint32_t& r2, uint32_t& r3)
{
    asm volatile("ldmatrix.sync.aligned.m8n8.x4.shared.b16 {%0,%1,%2,%3}, [%4];"
                 : "=r"(r0), "=r"(r1), "=r"(r2), "=r"(r3) : "r"(addr));
}
__device__ __forceinline__ void mma1688(float* d,
    uint32_t a0, uint32_t a1, uint32_t a2, uint32_t a3,
    uint32_t b0, uint32_t b1)
{
    asm volatile(
        "mma.sync.aligned.m16n8k8.row.col.f32.tf32.tf32.f32 "
        "{%0,%1,%2,%3}, {%4,%5,%6,%7}, {%8,%9}, {%0,%1,%2,%3};"
        : "+f"(d[0]), "+f"(d[1]), "+f"(d[2]), "+f"(d[3])
        : "r"(a0), "r"(a1), "r"(a2), "r"(a3), "r"(b0), "r"(b1));
}
// fp32 (as bits) -> tf32, round-to-nearest, applied on fragment registers.
__device__ __forceinline__ uint32_t tf32r(uint32_t w) {
    uint32_t u;
    asm("cvt.rna.tf32.f32 %0, %1;" : "=r"(u) : "f"(__uint_as_float(w)));
    return u;
}
__device__ __forceinline__ void cvt_frag4(uint32_t* r) {
    r[0] = tf32r(r[0]); r[1] = tf32r(r[1]); r[2] = tf32r(r[2]); r[3] = tf32r(r[3]);
}
// 16B async copy, zero-filled when sz==0 (row out of range)
__device__ __forceinline__ void cp16(uint32_t dst, const void* src, int sz) {
    asm volatile("cp.async.cg.shared.global [%0], [%1], 16, %2;"
                 :: "r"(dst), "l"(src), "r"(sz));
}
#define CP_COMMIT() asm volatile("cp.async.commit_group;")
#define CP_WAIT(n)  asm volatile("cp.async.wait_group %0;" :: "n"(n))

// ===========================================================================
// Grouped fused kernel, ALL 8 types in ONE launch.
// CTA tile 128 rows x 64 cols, 256 thr, 8 warps, warp tile 32x32, 3 CTAs/SM.
// tf32 GEMM + bias + threefry dropout. 2-stage cp.async double buffer.
// RNG: 32 keep-bits/thread. For ksteps>=4: FOUR unrolled 8-hash bursts in
// tiles 0..3 (flattens alu-pipe load — R14 was alu-bursty in tiles 0/1);
// for ksteps<4: two unrolled 16-hash bursts (tiles 0/1).
// ===========================================================================
#define RSW 36                        // smem row stride in words (144 B)
#define AW  (128 * RSW)
#define BW  (64 * RSW)
#define STG (AW + BW)
#define SMEM_BYTES (2 * STG * 4)      // 55296 B

struct Entry {
    const float* x;
    const float* W;
    const float* bias;
    float*       out;
    int N, C, ksteps, bstart;
    uint32_t k0, k1;
};
struct Params { Entry e[8]; };

__global__ __launch_bounds__(256, 3) void fused_all(Params p)
{
    extern __shared__ __align__(16) uint32_t sm[];

    const int bid = blockIdx.x;
    int t = 0;
#pragma unroll
    for (int i = 1; i < 8; i++)
        if (bid >= p.e[i].bstart) t = i;

    const float* __restrict__ x    = p.e[t].x;
    const float* __restrict__ W    = p.e[t].W;
    const float* __restrict__ bias = p.e[t].bias;
    float*       __restrict__ out  = p.e[t].out;
    const int N      = p.e[t].N;
    const int C      = p.e[t].C;
    const int ksteps = p.e[t].ksteps;
    const uint32_t k0 = p.e[t].k0, k1 = p.e[t].k1;
    const uint32_t ks2 = k0 ^ k1 ^ 0x1BD11BDAu;

    const int local = bid - p.e[t].bstart;
    const int base  = (local >> 1) * 128;
    const int colh  = (local & 1) * 64;

    const int tid  = threadIdx.x;
    const int lane = tid & 31;
    const int warp = tid >> 5;
    const int wm   = warp & 3;
    const int wn   = warp >> 2;

    const uint32_t uS = smem_u32(sm);

    const int r16  = lane & 15;
    const int hc16 = (lane >> 4) << 4;
    const int rowq = lane >> 2;
    const int colq = (lane & 3) * 2;
    const int colbase = colh + wn * 32;

    // hoisted ldmatrix bases (byte offsets within a stage)
    const uint32_t aBase0 = (uint32_t)((wm * 32 + r16) * 144 + hc16);
    const uint32_t bBase0 = (uint32_t)(AW * 4) + (uint32_t)((wn * 32 + r16) * 144 + hc16);

    // per-thread copy coords
    const int arow = tid >> 3;
    const int aq   = tid & 7;

    // RNG element-index base for this thread (row rowq, col colq within tile)
    const uint32_t ebase = (uint32_t)(base + wm * 32 + rowq) * 128u
                         + (uint32_t)(colbase + colq);

    float acc[2][4][4];
#pragma unroll
    for (int i = 0; i < 2; i++)
#pragma unroll
        for (int j = 0; j < 4; j++)
#pragma unroll
            for (int q = 0; q < 4; q++) acc[i][j][q] = 0.0f;

    uint32_t kmask = 0;
    const bool spread = (ksteps >= 4);

    // ---- issue tile 0 ----
    {
#pragma unroll
        for (int it = 0; it < 4; it++) {
            int row = arow + 32 * it;
            int gr  = base + row;
            cp16(uS + (uint32_t)(row * RSW + aq * 4) * 4,
                 x + (long)gr * C + aq * 4, (gr < N) ? 16 : 0);
        }
#pragma unroll
        for (int it = 0; it < 2; it++) {
            int row = arow + 32 * it;
            cp16(uS + (uint32_t)(AW + row * RSW + aq * 4) * 4,
                 W + (long)(colh + row) * C + aq * 4, 16);
        }
        CP_COMMIT();
    }

    for (int kt = 0; kt < ksteps; kt++) {
        const bool hn = (kt + 1) < ksteps;
        if (hn) {
            const int kb = (kt + 1) * 32;
            const uint32_t soff = (uint32_t)(((kt + 1) & 1) * STG) * 4;
#pragma unroll
            for (int it = 0; it < 4; it++) {
                int row = arow + 32 * it;
                int gr  = base + row;
                cp16(uS + soff + (uint32_t)(row * RSW + aq * 4) * 4,
                     x + (long)gr * C + kb + aq * 4, (gr < N) ? 16 : 0);
            }
#pragma unroll
            for (int it = 0; it < 2; it++) {
                int row = arow + 32 * it;
                cp16(uS + soff + (uint32_t)(AW + row * RSW + aq * 4) * 4,
                     W + (long)(colh + row) * C + kb + aq * 4, 16);
            }
            CP_COMMIT();
        }

        // ---- dropout-mask bursts (fully unrolled, uniform guards) ----
        // bit i (0..31): am=i>>4 (16-row group), an=(i>>2)&3, rp=(i>>1)&1, cp=i&1
        if (spread) {
            if (kt < 4) {
                uint32_t m = 0;
#pragma unroll
                for (int j = 0; j < 8; j++) {
                    int i  = kt * 8 + j;
                    int am = i >> 4, an = (i >> 2) & 3, rp = (i >> 1) & 1, cp = i & 1;
                    uint32_t e = ebase + (uint32_t)((am * 16 + rp * 8) * 128 + an * 8 + cp);
                    m |= tf_keep(k0, k1, ks2, e) << j;
                }
                kmask |= m << (kt * 8);
            }
        } else {
            if (kt < 2) {
                uint32_t m = 0;
#pragma unroll
                for (int j = 0; j < 16; j++) {
                    int i  = kt * 16 + j;
                    int am = i >> 4, an = (i >> 2) & 3, rp = (i >> 1) & 1, cp = i & 1;
                    uint32_t e = ebase + (uint32_t)((am * 16 + rp * 8) * 128 + an * 8 + cp);
                    m |= tf_keep(k0, k1, ks2, e) << j;
                }
                kmask |= m << (kt * 16);
            }
        }

        if (hn) CP_WAIT(1); else CP_WAIT(0);
        __syncthreads();

        // ---- MMA on stage kt&1: 4 chunks of 8 fp32-k ----
        const uint32_t sS = uS + (uint32_t)((kt & 1) * STG) * 4;
#pragma unroll
        for (int c8 = 0; c8 < 4; c8++) {
            const uint32_t coff = (uint32_t)(c8 * 32);

            uint32_t ah[2][4];
#pragma unroll
            for (int am = 0; am < 2; am++) {
                ldm4(sS + aBase0 + coff + (uint32_t)(am * 16 * 144),
                     ah[am][0], ah[am][1], ah[am][2], ah[am][3]);
                cvt_frag4(ah[am]);
            }

            uint32_t b[2][4];
#pragma unroll
            for (int pg = 0; pg < 2; pg++) {
                ldm4(sS + bBase0 + coff + (uint32_t)(pg * 16 * 144),
                     b[pg][0], b[pg][1], b[pg][2], b[pg][3]);
                cvt_frag4(b[pg]);
            }

#pragma unroll
            for (int am = 0; am < 2; am++)
#pragma unroll
                for (int pg = 0; pg < 2; pg++) {
                    mma1688(acc[am][2 * pg],     ah[am][0], ah[am][1], ah[am][2], ah[am][3], b[pg][0], b[pg][2]);
                    mma1688(acc[am][2 * pg + 1], ah[am][0], ah[am][1], ah[am][2], ah[am][3], b[pg][1], b[pg][3]);
                }
        }
        __syncthreads();
    }

    // ---- epilogue: bias + masked scale + store ----
    // mask bit i = am*16 + an*4 + rp*2 + cp
#pragma unroll
    for (int am = 0; am < 2; am++) {
        int row0 = base + wm * 32 + am * 16 + rowq;
#pragma unroll
        for (int an = 0; an < 4; an++) {
            int col = colbase + an * 8 + colq;
            float b0 = __ldg(bias + col);
            float b1 = __ldg(bias + col + 1);
#pragma unroll
            for (int rp = 0; rp < 2; rp++) {
                int row = row0 + rp * 8;
                if (row < N) {
                    int i0 = am * 16 + an * 4 + rp * 2;
                    uint32_t bit0 = (kmask >> i0) & 1u;
                    uint32_t bit1 = (kmask >> (i0 + 1)) & 1u;
                    float y0 = acc[am][an][rp * 2 + 0] + b0;
                    float y1 = acc[am][an][rp * 2 + 1] + b1;
                    float2 v;
                    v.x = bit0 ? y0 * 1.25f : 0.0f;
                    v.y = bit1 ? y1 * 1.25f : 0.0f;
                    *(float2*)(out + (size_t)row * 128 + col) = v;
                }
            }
        }
    }
}

// ===========================================================================
// Launch: ONE grouped kernel; 2 blocks (col halves) per 128-row tile.
// ===========================================================================
static const int C_TAB[8] = {128, 256, 64, 128, 192, 96, 160, 128};

extern "C" void kernel_launch(void* const* d_in, const int* in_sizes, int n_in,
                              void* d_out, int out_size)
{
    (void)n_in; (void)out_size;
    const bool interleaved = (in_sizes[1] == 128 * C_TAB[0]);

    static bool attr_set = false;
    if (!attr_set) {
        cudaFuncSetAttribute(fused_all,
                             cudaFuncAttributeMaxDynamicSharedMemorySize, SMEM_BYTES);
        attr_set = true;
    }

    Params p;
    size_t off = 0;
    int bstart = 0;
    for (int t = 0; t < 8; t++) {
        const int C = C_TAB[t];
        const int xi = interleaved ? (3 * t)     : t;
        const int wi = interleaved ? (3 * t + 1) : (8 + t);
        const int bi = interleaved ? (3 * t + 2) : (16 + t);
        const int N  = in_sizes[xi] / C;

        uint32_t fk0, fk1;
        threefry2x32_host(0u, 42u, 0u, (uint32_t)t, fk0, fk1);

        p.e[t].x      = (const float*)d_in[xi];
        p.e[t].W      = (const float*)d_in[wi];
        p.e[t].bias   = (const float*)d_in[bi];
        p.e[t].out    = (float*)d_out + off;
        p.e[t].N      = N;
        p.e[t].C      = C;
        p.e[t].ksteps = C / 32;
        p.e[t].bstart = bstart;
        p.e[t].k0     = fk0;
        p.e[t].k1     = fk1;

        bstart += 2 * ((N + 127) / 128);
        off += (size_t)N * 128;
    }

    fused_all<<<bstart, 256, SMEM_BYTES>>>(p);
}

// round 17
// speedup vs baseline: 1.0402x; 1.0402x over previous
#include <cuda_runtime.h>
#include <stdint.h>

// ===========================================================================
// JAX threefry2x32 (exact)
// ===========================================================================
static void threefry2x32_host(
    uint32_t k0, uint32_t k1, uint32_t x0, uint32_t x1,
    uint32_t& o0, uint32_t& o1)
{
    uint32_t ks2 = k0 ^ k1 ^ 0x1BD11BDAu;
    x0 += k0; x1 += k1;
#define TF_RNDH(R) { x0 += x1; x1 = (x1 << (R)) | (x1 >> (32 - (R))); x1 ^= x0; }
    TF_RNDH(13) TF_RNDH(15) TF_RNDH(26) TF_RNDH(6)   x0 += k1;  x1 += ks2 + 1u;
    TF_RNDH(17) TF_RNDH(29) TF_RNDH(16) TF_RNDH(24)  x0 += ks2; x1 += k0  + 2u;
    TF_RNDH(13) TF_RNDH(15) TF_RNDH(26) TF_RNDH(6)   x0 += k0;  x1 += k1  + 3u;
    TF_RNDH(17) TF_RNDH(29) TF_RNDH(16) TF_RNDH(24)  x0 += k1;  x1 += ks2 + 4u;
    TF_RNDH(13) TF_RNDH(15) TF_RNDH(26) TF_RNDH(6)   x0 += ks2; x1 += k0  + 5u;
#undef TF_RNDH
    o0 = x0; o1 = x1;
}

// keep-decision for flat element e: partitionable threefry counter (0, e),
// XOR-fold, uniform<0.8f as EXACT integer compare: bits < 0xCCCCCE00 (R9-verified)
__device__ __forceinline__ uint32_t tf_keep(uint32_t k0, uint32_t k1, uint32_t ks2,
                                            uint32_t e)
{
    uint32_t x0 = k0, x1 = e + k1;
#define TF_RND(R) { x0 += x1; x1 = __funnelshift_l(x1, x1, R); x1 ^= x0; }
    TF_RND(13) TF_RND(15) TF_RND(26) TF_RND(6)   x0 += k1;  x1 += ks2 + 1u;
    TF_RND(17) TF_RND(29) TF_RND(16) TF_RND(24)  x0 += ks2; x1 += k0  + 2u;
    TF_RND(13) TF_RND(15) TF_RND(26) TF_RND(6)   x0 += k0;  x1 += k1  + 3u;
    TF_RND(17) TF_RND(29) TF_RND(16) TF_RND(24)  x0 += k1;  x1 += ks2 + 4u;
    TF_RND(13) TF_RND(15) TF_RND(26) TF_RND(6)   x0 += ks2; x1 += k0  + 5u;
#undef TF_RND
    return ((x0 ^ x1) < 0xCCCCCE00u) ? 1u : 0u;
}

// ===========================================================================
// Primitives (baseline PTX — valid on compute_103 non-'a')
// ===========================================================================
__device__ __forceinline__ uint32_t smem_u32(const void* p) {
    uint32_t a;
    asm("{ .reg .u64 t; cvta.to.shared.u64 t, %1; cvt.u32.u64 %0, t; }"
        : "=r"(a) : "l"(p));
    return a;
}
__device__ __forceinline__ void ldm4(uint32_t addr,
    uint32_t& r0, uint32_t& r1, uint32_t& r2, uint32_t& r3)
{
    asm volatile("ldmatrix.sync.aligned.m8n8.x4.shared.b16 {%0,%1,%2,%3}, [%4];"
                 : "=r"(r0), "=r"(r1), "=r"(r2), "=r"(r3) : "r"(addr));
}
__device__ __forceinline__ void mma1688(float* d,
    uint32_t a0, uint32_t a1, uint32_t a2, uint32_t a3,
    uint32_t b0, uint32_t b1)
{
    asm volatile(
        "mma.sync.aligned.m16n8k8.row.col.f32.tf32.tf32.f32 "
        "{%0,%1,%2,%3}, {%4,%5,%6,%7}, {%8,%9}, {%0,%1,%2,%3};"
        : "+f"(d[0]), "+f"(d[1]), "+f"(d[2]), "+f"(d[3])
        : "r"(a0), "r"(a1), "r"(a2), "r"(a3), "r"(b0), "r"(b1));
}
// fp32 (as bits) -> tf32, round-to-nearest (RNA)
__device__ __forceinline__ uint32_t tf32r(uint32_t w) {
    uint32_t u;
    asm("cvt.rna.tf32.f32 %0, %1;" : "=r"(u) : "f"(__uint_as_float(w)));
    return u;
}
__device__ __forceinline__ void cvt_frag4(uint32_t* r) {
    r[0] = tf32r(r[0]); r[1] = tf32r(r[1]); r[2] = tf32r(r[2]); r[3] = tf32r(r[3]);
}
// 16B async copy, zero-filled when sz==0
__device__ __forceinline__ void cp16(uint32_t dst, const void* src, int sz) {
    asm volatile("cp.async.cg.shared.global [%0], [%1], 16, %2;"
                 :: "r"(dst), "l"(src), "r"(sz));
}
#define CP_COMMIT() asm volatile("cp.async.commit_group;")
#define CP_WAIT0()  asm volatile("cp.async.wait_group 0;")

// ===========================================================================
// Pre-rounded W scratch: sum(128*C) = 128*1152 = 147456 floats (576 KB).
// W is tf32-RNA-rounded ONCE here; main kernel B fragments then need no cvt
// (arithmetic identical to rounding in-loop).
// ===========================================================================
__device__ float g_Wr[147456];

struct WPre { const float* w[8]; int off[8]; int len[8]; };

__global__ __launch_bounds__(256) void preround_W(WPre wp)
{
    int gid = blockIdx.x * 256 + threadIdx.x;   // float4 index
    int idx = gid * 4;
    // locate segment
#pragma unroll
    for (int t = 0; t < 8; t++) {
        int o = wp.off[t], L = wp.len[t];
        if (idx >= o && idx < o + L) {
            const float4 v = *(const float4*)(wp.w[t] + (idx - o));
            uint4 r;
            r.x = tf32r(__float_as_uint(v.x));
            r.y = tf32r(__float_as_uint(v.y));
            r.z = tf32r(__float_as_uint(v.z));
            r.w = tf32r(__float_as_uint(v.w));
            *(uint4*)(g_Wr + idx) = r;
        }
    }
}

// ===========================================================================
// Grouped fused kernel, ALL 8 types in ONE launch.
// CTA tile 128 rows x 64 cols, 256 thr, 8 warps, warp tile 32x32, 3 CTAs/SM.
// tf32 GEMM + bias + threefry dropout. 2-stage cp.async double buffer with
// ONE __syncthreads per k-tile (wait -> sync -> issue-next -> RNG -> MMA;
// the sync proves the previous MMA finished before its buffer is rewritten).
// A fragments tf32-rounded in-register; B comes pre-rounded from g_Wr.
// RNG: two fully-unrolled 16-hash bursts in k-tiles 0/1 (R14 schedule).
// ===========================================================================
#define RSW 36                        // smem row stride in words (144 B)
#define AW  (128 * RSW)
#define BW  (64 * RSW)
#define STG (AW + BW)
#define SMEM_BYTES (2 * STG * 4)      // 55296 B

struct Entry {
    const float* x;
    const float* bias;
    float*       out;
    int N, C, ksteps, bstart, woff;
    uint32_t k0, k1;
};
struct Params { Entry e[8]; };

__global__ __launch_bounds__(256, 3) void fused_all(Params p)
{
    extern __shared__ __align__(16) uint32_t sm[];

    const int bid = blockIdx.x;
    int t = 0;
#pragma unroll
    for (int i = 1; i < 8; i++)
        if (bid >= p.e[i].bstart) t = i;

    const float* __restrict__ x    = p.e[t].x;
    const float* __restrict__ Wr   = g_Wr + p.e[t].woff;
    const float* __restrict__ bias = p.e[t].bias;
    float*       __restrict__ out  = p.e[t].out;
    const int N      = p.e[t].N;
    const int C      = p.e[t].C;
    const int ksteps = p.e[t].ksteps;
    const uint32_t k0 = p.e[t].k0, k1 = p.e[t].k1;
    const uint32_t ks2 = k0 ^ k1 ^ 0x1BD11BDAu;

    const int local = bid - p.e[t].bstart;
    const int base  = (local >> 1) * 128;
    const int colh  = (local & 1) * 64;

    const int tid  = threadIdx.x;
    const int lane = tid & 31;
    const int warp = tid >> 5;
    const int wm   = warp & 3;
    const int wn   = warp >> 2;

    const uint32_t uS = smem_u32(sm);

    const int r16  = lane & 15;
    const int hc16 = (lane >> 4) << 4;
    const int rowq = lane >> 2;
    const int colq = (lane & 3) * 2;
    const int colbase = colh + wn * 32;

    const uint32_t aBase0 = (uint32_t)((wm * 32 + r16) * 144 + hc16);
    const uint32_t bBase0 = (uint32_t)(AW * 4) + (uint32_t)((wn * 32 + r16) * 144 + hc16);

    const int arow = tid >> 3;
    const int aq   = tid & 7;

    const uint32_t ebase = (uint32_t)(base + wm * 32 + rowq) * 128u
                         + (uint32_t)(colbase + colq);

    float acc[2][4][4];
#pragma unroll
    for (int i = 0; i < 2; i++)
#pragma unroll
        for (int j = 0; j < 4; j++)
#pragma unroll
            for (int q = 0; q < 4; q++) acc[i][j][q] = 0.0f;

    uint32_t kmask = 0;

    // ---- issue tile 0 ----
    {
#pragma unroll
        for (int it = 0; it < 4; it++) {
            int row = arow + 32 * it;
            int gr  = base + row;
            cp16(uS + (uint32_t)(row * RSW + aq * 4) * 4,
                 x + (long)gr * C + aq * 4, (gr < N) ? 16 : 0);
        }
#pragma unroll
        for (int it = 0; it < 2; it++) {
            int row = arow + 32 * it;
            cp16(uS + (uint32_t)(AW + row * RSW + aq * 4) * 4,
                 Wr + (long)(colh + row) * C + aq * 4, 16);
        }
        CP_COMMIT();
    }

    for (int kt = 0; kt < ksteps; kt++) {
        CP_WAIT0();            // tile kt's copies landed (only outstanding group)
        __syncthreads();       // + all warps done with MMA(kt-1): safe to refill

        if ((kt + 1) < ksteps) {
            const int kb = (kt + 1) * 32;
            const uint32_t soff = (uint32_t)(((kt + 1) & 1) * STG) * 4;
#pragma unroll
            for (int it = 0; it < 4; it++) {
                int row = arow + 32 * it;
                int gr  = base + row;
                cp16(uS + soff + (uint32_t)(row * RSW + aq * 4) * 4,
                     x + (long)gr * C + kb + aq * 4, (gr < N) ? 16 : 0);
            }
#pragma unroll
            for (int it = 0; it < 2; it++) {
                int row = arow + 32 * it;
                cp16(uS + soff + (uint32_t)(AW + row * RSW + aq * 4) * 4,
                     Wr + (long)(colh + row) * C + kb + aq * 4, 16);
            }
            CP_COMMIT();
        }

        // ---- dropout mask burst: 16 keep-bits in k-tiles 0 and 1 ----
        // bit i = am*16 + an*4 + rp*2 + cp  (am = kt for these two tiles)
        if (kt < 2) {
            uint32_t m = 0;
#pragma unroll
            for (int j = 0; j < 16; j++) {
                int an = j >> 2, rp = (j >> 1) & 1, cp = j & 1;
                uint32_t e = ebase + (uint32_t)((kt * 16 + rp * 8) * 128 + an * 8 + cp);
                m |= tf_keep(k0, k1, ks2, e) << j;
            }
            kmask |= m << (kt * 16);
        }

        // ---- MMA on stage kt&1: 4 chunks of 8 fp32-k ----
        const uint32_t sS = uS + (uint32_t)((kt & 1) * STG) * 4;
#pragma unroll
        for (int c8 = 0; c8 < 4; c8++) {
            const uint32_t coff = (uint32_t)(c8 * 32);

            uint32_t ah[2][4];
#pragma unroll
            for (int am = 0; am < 2; am++) {
                ldm4(sS + aBase0 + coff + (uint32_t)(am * 16 * 144),
                     ah[am][0], ah[am][1], ah[am][2], ah[am][3]);
                cvt_frag4(ah[am]);
            }

            uint32_t b[2][4];
#pragma unroll
            for (int pg = 0; pg < 2; pg++)
                ldm4(sS + bBase0 + coff + (uint32_t)(pg * 16 * 144),
                     b[pg][0], b[pg][1], b[pg][2], b[pg][3]);   // pre-rounded

#pragma unroll
            for (int am = 0; am < 2; am++)
#pragma unroll
                for (int pg = 0; pg < 2; pg++) {
                    mma1688(acc[am][2 * pg],     ah[am][0], ah[am][1], ah[am][2], ah[am][3], b[pg][0], b[pg][2]);
                    mma1688(acc[am][2 * pg + 1], ah[am][0], ah[am][1], ah[am][2], ah[am][3], b[pg][1], b[pg][3]);
                }
        }
    }

    __syncthreads();   // MMA done before exit epilogue (uses regs only; keeps buffers safe)

    // ---- epilogue: bias + masked scale + store ----
#pragma unroll
    for (int am = 0; am < 2; am++) {
        int row0 = base + wm * 32 + am * 16 + rowq;
#pragma unroll
        for (int an = 0; an < 4; an++) {
            int col = colbase + an * 8 + colq;
            float b0 = __ldg(bias + col);
            float b1 = __ldg(bias + col + 1);
#pragma unroll
            for (int rp = 0; rp < 2; rp++) {
                int row = row0 + rp * 8;
                if (row < N) {
                    int i0 = am * 16 + an * 4 + rp * 2;
                    uint32_t bit0 = (kmask >> i0) & 1u;
                    uint32_t bit1 = (kmask >> (i0 + 1)) & 1u;
                    float y0 = acc[am][an][rp * 2 + 0] + b0;
                    float y1 = acc[am][an][rp * 2 + 1] + b1;
                    float2 v;
                    v.x = bit0 ? y0 * 1.25f : 0.0f;
                    v.y = bit1 ? y1 * 1.25f : 0.0f;
                    *(float2*)(out + (size_t)row * 128 + col) = v;
                }
            }
        }
    }
}

// ===========================================================================
// Launch: preround_W then ONE grouped kernel.
// ===========================================================================
static const int C_TAB[8] = {128, 256, 64, 128, 192, 96, 160, 128};

extern "C" void kernel_launch(void* const* d_in, const int* in_sizes, int n_in,
                              void* d_out, int out_size)
{
    (void)n_in; (void)out_size;
    const bool interleaved = (in_sizes[1] == 128 * C_TAB[0]);

    static bool attr_set = false;
    if (!attr_set) {
        cudaFuncSetAttribute(fused_all,
                             cudaFuncAttributeMaxDynamicSharedMemorySize, SMEM_BYTES);
        attr_set = true;
    }

    Params p;
    WPre wp;
    size_t off = 0;
    int bstart = 0, woff = 0;
    for (int t = 0; t < 8; t++) {
        const int C = C_TAB[t];
        const int xi = interleaved ? (3 * t)     : t;
        const int wi = interleaved ? (3 * t + 1) : (8 + t);
        const int bi = interleaved ? (3 * t + 2) : (16 + t);
        const int N  = in_sizes[xi] / C;

        uint32_t fk0, fk1;
        threefry2x32_host(0u, 42u, 0u, (uint32_t)t, fk0, fk1);

        wp.w[t]   = (const float*)d_in[wi];
        wp.off[t] = woff;
        wp.len[t] = 128 * C;

        p.e[t].x      = (const float*)d_in[xi];
        p.e[t].bias   = (const float*)d_in[bi];
        p.e[t].out    = (float*)d_out + off;
        p.e[t].N      = N;
        p.e[t].C      = C;
        p.e[t].ksteps = C / 32;
        p.e[t].bstart = bstart;
        p.e[t].woff   = woff;
        p.e[t].k0     = fk0;
        p.e[t].k1     = fk1;

        bstart += 2 * ((N + 127) / 128);
        woff   += 128 * C;
        off    += (size_t)N * 128;
    }

    preround_W<<<(147456 / 4 + 255) / 256, 256>>>(wp);
    fused_all<<<bstart, 256, SMEM_BYTES>>>(p);
}